// round 11
// baseline (speedup 1.0000x reference)
#include <cuda_runtime.h>
#include <cstdint>

#define N_MAX 50000
#define M_MAX 800000
#define D 128
#define SCAN_BS 512

// Scratch — __device__ globals only (no allocs allowed).
__device__ __align__(16) static float g_xn[N_MAX * D];     // normalized layer input
__device__ __align__(16) static float g_c[N_MAX * D];      // current normalized routing state
__device__ __align__(16) static float g_cnew[N_MAX * D];   // layer output (unnormalized)
__device__ static int g_src[M_MAX];
__device__ static int g_trg[M_MAX];
__device__ static int g_deg[N_MAX];
__device__ static int g_cnt[N_MAX];
__device__ static int g_tmp[N_MAX];          // block-local exclusive scan
__device__ static int g_bsum[256];           // per-block sums
__device__ static int g_adj[M_MAX];          // incoming-edge src ids grouped by trg

// -------------------------------------------- idx convert + degree histogram
// edge_index is int32 (established: int64 interpretation faults; int32 passes).
__global__ void idx_hist_kernel(const int* __restrict__ ei,
                                int* __restrict__ src, int* __restrict__ trg,
                                int* __restrict__ deg, int m) {
    int i = blockIdx.x * blockDim.x + threadIdx.x;
    if (i >= m) return;
    int s = ei[i];
    int t = ei[m + i];
    src[i] = s;
    trg[i] = t;
    atomicAdd(&deg[t], 1);
}

// Phase 1: per-block exclusive scan (Hillis-Steele) + block sum.
__global__ void scan_block_kernel(const int* __restrict__ deg, int* __restrict__ tmp,
                                  int* __restrict__ bsum, int n) {
    __shared__ int sm[SCAN_BS];
    int t = threadIdx.x;
    int i = blockIdx.x * SCAN_BS + t;
    int v = (i < n) ? deg[i] : 0;
    sm[t] = v;
    __syncthreads();
    for (int off = 1; off < SCAN_BS; off <<= 1) {
        int y = (t >= off) ? sm[t - off] : 0;
        __syncthreads();
        sm[t] += y;
        __syncthreads();
    }
    if (i < n) tmp[i] = sm[t] - v;              // exclusive
    if (t == SCAN_BS - 1) bsum[blockIdx.x] = sm[t];
}

// Phase 2: exclusive scan of block sums (nb <= 256), single block.
__global__ void scan_bsum_kernel(int* __restrict__ bsum, int nb) {
    __shared__ int sm[256];
    int t = threadIdx.x;
    int v = (t < nb) ? bsum[t] : 0;
    sm[t] = v;
    __syncthreads();
    for (int off = 1; off < 256; off <<= 1) {
        int y = (t >= off) ? sm[t - off] : 0;
        __syncthreads();
        sm[t] += y;
        __syncthreads();
    }
    if (t < nb) bsum[t] = sm[t] - v;            // exclusive
}

// Scatter: rowptr computed inline as tmp[tg] + bsum[tg>>9].
__global__ void scatter_kernel(const int* __restrict__ src, const int* __restrict__ trg,
                               const int* __restrict__ tmp, const int* __restrict__ bsum,
                               int* __restrict__ cnt, int* __restrict__ adj, int m) {
    int i = blockIdx.x * blockDim.x + threadIdx.x;
    if (i >= m) return;
    int tg = trg[i];
    int pos = tmp[tg] + bsum[tg >> 9] + atomicAdd(&cnt[tg], 1);
    adj[pos] = src[i];
}

// ------------------------------------- GEMM + bias + fused channel-normalize
// C[n,128] = normalize_channels(A @ W + b). Thread j holds column j for 32 rows;
// warp w = j/32 holds exactly channel w of each row -> 32-lane shfl reduce per row.
// Blocks beyond the gemm range zero deg/cnt (replaces two memsets).
#define BM 32
__global__ void gemm_norm_zero_kernel(const float* __restrict__ A,
                                      const float* __restrict__ W,
                                      const float* __restrict__ b,
                                      float* __restrict__ C, int n,
                                      int* __restrict__ deg, int* __restrict__ cnt) {
    int G1 = (n + BM - 1) / BM;
    if (blockIdx.x >= G1) {
        int i = (blockIdx.x - G1) * blockDim.x + threadIdx.x;
        if (i < n) { deg[i] = 0; cnt[i] = 0; }
        return;
    }
    __shared__ float As[BM * D];
    int j = threadIdx.x;
    int row0 = blockIdx.x * BM;
    int nvalid = n - row0; if (nvalid > BM) nvalid = BM;

    const float4* A4 = (const float4*)(A + (size_t)row0 * D);
    float4* As4 = (float4*)As;
    for (int i = threadIdx.x; i < nvalid * (D / 4); i += blockDim.x) As4[i] = A4[i];
    __syncthreads();

    float acc[BM];
#pragma unroll
    for (int r = 0; r < BM; r++) acc[r] = 0.f;
    for (int k = 0; k < D; k++) {
        float w = W[k * D + j];
#pragma unroll
        for (int r = 0; r < BM; r++) acc[r] = fmaf(As[r * D + k], w, acc[r]);
    }
    float bj = b[j];
    for (int r = 0; r < nvalid; r++) {
        float val = acc[r] + bj;
        float ss = val * val;
        ss += __shfl_xor_sync(0xffffffffu, ss, 1);
        ss += __shfl_xor_sync(0xffffffffu, ss, 2);
        ss += __shfl_xor_sync(0xffffffffu, ss, 4);
        ss += __shfl_xor_sync(0xffffffffu, ss, 8);
        ss += __shfl_xor_sync(0xffffffffu, ss, 16);
        float inv = 1.0f / fmaxf(sqrtf(ss), 1e-12f);
        C[(size_t)(row0 + r) * D + j] = val * inv;
    }
}

// ---------------------------------------------------- plain GEMM + bias (output)
__global__ void gemm_bias_kernel(const float* __restrict__ A,
                                 const float* __restrict__ W,
                                 const float* __restrict__ b,
                                 float* __restrict__ C, int n) {
    __shared__ float As[BM * D];
    int j = threadIdx.x;
    int row0 = blockIdx.x * BM;
    int nvalid = n - row0; if (nvalid > BM) nvalid = BM;

    const float4* A4 = (const float4*)(A + (size_t)row0 * D);
    float4* As4 = (float4*)As;
    for (int i = threadIdx.x; i < nvalid * (D / 4); i += blockDim.x) As4[i] = A4[i];
    __syncthreads();

    float acc[BM];
#pragma unroll
    for (int r = 0; r < BM; r++) acc[r] = 0.f;
    for (int k = 0; k < D; k++) {
        float w = W[k * D + j];
#pragma unroll
        for (int r = 0; r < BM; r++) acc[r] = fmaf(As[r * D + k], w, acc[r]);
    }
    float bj = b[j];
    for (int r = 0; r < nvalid; r++) C[(size_t)(row0 + r) * D + j] = acc[r] + bj;
}

// ------------------------------------------------------- channel normalize
__global__ void norm_kernel(const float* __restrict__ in, float* __restrict__ out, int n) {
    int gw = (blockIdx.x * blockDim.x + threadIdx.x) >> 5;
    if (gw >= n) return;
    int lane = threadIdx.x & 31;
    float4 v = *(const float4*)(in + (size_t)gw * D + lane * 4);
    float ss = v.x * v.x + v.y * v.y + v.z * v.z + v.w * v.w;
    ss += __shfl_xor_sync(0xffffffffu, ss, 1);
    ss += __shfl_xor_sync(0xffffffffu, ss, 2);
    ss += __shfl_xor_sync(0xffffffffu, ss, 4);
    float inv = 1.0f / fmaxf(sqrtf(ss), 1e-12f);
    *(float4*)(out + (size_t)gw * D + lane * 4) =
        make_float4(v.x * inv, v.y * inv, v.z * inv, v.w * inv);
}

// ------------------------------------------- fused routing iteration (R9 body)
// warp per target node v; TWO edges per warp-iteration (16 lanes each).
// beg = tmp[v] + bsum[v>>9]; end = beg + deg[v]  (rowptr computed inline).
template <bool DO_NORM>
__global__ void iter_kernel(const int* __restrict__ tmp, const int* __restrict__ bsum,
                            const int* __restrict__ deg, const int* __restrict__ adj,
                            const float* __restrict__ xn, const float* __restrict__ c,
                            float* __restrict__ out, int n) {
    int v = (blockIdx.x * blockDim.x + threadIdx.x) >> 5;
    if (v >= n) return;
    int lane = threadIdx.x & 31;
    int half = lane >> 4;
    int q = lane & 3;
    int ch = (lane & 15) >> 2;
    int dbase = ch * 32 + q * 8;

    // s[a] = sum of c[v][4a..4a+3]; lane a holds sv. Redistribute 8 per lane.
    float4 cv = *(const float4*)(c + (size_t)v * D + lane * 4);
    float sv = cv.x + cv.y + cv.z + cv.w;
    float sr[8];
#pragma unroll
    for (int j = 0; j < 8; j++)
        sr[j] = __shfl_sync(0xffffffffu, sv, q * 8 + j);

    // residual into half 0 only (merge would double-count otherwise)
    float4 a0 = make_float4(0.f, 0.f, 0.f, 0.f);
    float4 a1 = make_float4(0.f, 0.f, 0.f, 0.f);
    if (half == 0) {
        a0 = *(const float4*)(xn + (size_t)v * D + dbase);
        a1 = *(const float4*)(xn + (size_t)v * D + dbase + 4);
    }

    int beg = tmp[v] + bsum[v >> 9];
    int end = beg + deg[v];
    int nit = (end - beg + 1) >> 1;
    for (int j = 0; j < nit; j++) {
        int e = beg + 2 * j + half;
        bool valid = (e < end);
        int s = adj[valid ? e : beg];
        const float* zp = xn + (size_t)s * D + dbase;
        float4 z0 = *(const float4*)(zp);
        float4 z1 = *(const float4*)(zp + 4);

        float p = z0.x * sr[0] + z0.y * sr[1] + z0.z * sr[2] + z0.w * sr[3]
                + z1.x * sr[4] + z1.y * sr[5] + z1.z * sr[6] + z1.w * sr[7];
        p += __shfl_xor_sync(0xffffffffu, p, 1);
        p += __shfl_xor_sync(0xffffffffu, p, 2);       // p = logit for channel ch
        float mx = fmaxf(p, __shfl_xor_sync(0xffffffffu, p, 4));
        mx = fmaxf(mx, __shfl_xor_sync(0xffffffffu, mx, 8));
        float ex = __expf(p - mx);
        float den = ex + __shfl_xor_sync(0xffffffffu, ex, 4);
        den += __shfl_xor_sync(0xffffffffu, den, 8);
        float w = valid ? __fdividef(ex, den) : 0.f;

        a0.x = fmaf(w, z0.x, a0.x);
        a0.y = fmaf(w, z0.y, a0.y);
        a0.z = fmaf(w, z0.z, a0.z);
        a0.w = fmaf(w, z0.w, a0.w);
        a1.x = fmaf(w, z1.x, a1.x);
        a1.y = fmaf(w, z1.y, a1.y);
        a1.z = fmaf(w, z1.z, a1.z);
        a1.w = fmaf(w, z1.w, a1.w);
    }

    // merge halves
    a0.x += __shfl_xor_sync(0xffffffffu, a0.x, 16);
    a0.y += __shfl_xor_sync(0xffffffffu, a0.y, 16);
    a0.z += __shfl_xor_sync(0xffffffffu, a0.z, 16);
    a0.w += __shfl_xor_sync(0xffffffffu, a0.w, 16);
    a1.x += __shfl_xor_sync(0xffffffffu, a1.x, 16);
    a1.y += __shfl_xor_sync(0xffffffffu, a1.y, 16);
    a1.z += __shfl_xor_sync(0xffffffffu, a1.z, 16);
    a1.w += __shfl_xor_sync(0xffffffffu, a1.w, 16);

    if (DO_NORM) {
        float ss = a0.x * a0.x + a0.y * a0.y + a0.z * a0.z + a0.w * a0.w
                 + a1.x * a1.x + a1.y * a1.y + a1.z * a1.z + a1.w * a1.w;
        ss += __shfl_xor_sync(0xffffffffu, ss, 1);
        ss += __shfl_xor_sync(0xffffffffu, ss, 2);
        float inv = 1.0f / fmaxf(sqrtf(ss), 1e-12f);
        a0.x *= inv; a0.y *= inv; a0.z *= inv; a0.w *= inv;
        a1.x *= inv; a1.y *= inv; a1.z *= inv; a1.w *= inv;
    }

    if (half == 0) {
        *(float4*)(out + (size_t)v * D + dbase)     = a0;
        *(float4*)(out + (size_t)v * D + dbase + 4) = a1;
    }
}

// ---------------------------------------------------------------- launch
extern "C" void kernel_launch(void* const* d_in, const int* in_sizes, int n_in,
                              void* d_out, int out_size) {
    const float* feat  = (const float*)d_in[0];
    const int*   ei    = (const int*)d_in[1];
    const float* lin_w = (const float*)d_in[2];
    const float* lin_b = (const float*)d_in[3];
    const float* mlp_w = (const float*)d_in[4];
    const float* mlp_b = (const float*)d_in[5];

    int n = in_sizes[0] / D;
    int m = in_sizes[1] / 2;

    float *xn, *c, *cnew;
    int *src, *trg, *deg, *cnt, *tmp, *bsum, *adj;
    cudaGetSymbolAddress((void**)&xn,     g_xn);
    cudaGetSymbolAddress((void**)&c,      g_c);
    cudaGetSymbolAddress((void**)&cnew,   g_cnew);
    cudaGetSymbolAddress((void**)&src,    g_src);
    cudaGetSymbolAddress((void**)&trg,    g_trg);
    cudaGetSymbolAddress((void**)&deg,    g_deg);
    cudaGetSymbolAddress((void**)&cnt,    g_cnt);
    cudaGetSymbolAddress((void**)&tmp,    g_tmp);
    cudaGetSymbolAddress((void**)&bsum,   g_bsum);
    cudaGetSymbolAddress((void**)&adj,    g_adj);

    int G1 = (n + BM - 1) / BM;
    int Gz = (n + 127) / 128;
    int node_blocks = (n * 32 + 255) / 256;  // warp per node
    int nb = (n + SCAN_BS - 1) / SCAN_BS;
    size_t nbytes = (size_t)n * D * sizeof(float);

    // (1) x = normalize(feat @ lin_w + lin_b) -> xn ; also zeros deg/cnt
    gemm_norm_zero_kernel<<<G1 + Gz, 128>>>(feat, lin_w, lin_b, xn, n, deg, cnt);
    // (2) edge convert + degree histogram
    idx_hist_kernel<<<(m + 255) / 256, 256>>>(ei, src, trg, deg, m);
    // (3,4) scan
    scan_block_kernel<<<nb, SCAN_BS>>>(deg, tmp, bsum, n);
    scan_bsum_kernel<<<1, 256>>>(bsum, nb);
    // (5) CSR scatter (rowptr inline)
    scatter_kernel<<<(m + 255) / 256, 256>>>(src, trg, tmp, bsum, cnt, adj, m);

    // (6..8) layer 1 routing   -- launch #6 is iter#1 (profiled by ncu -s 5)
    iter_kernel<true ><<<node_blocks, 256>>>(tmp, bsum, deg, adj, xn, xn, c, n);
    iter_kernel<true ><<<node_blocks, 256>>>(tmp, bsum, deg, adj, xn, c, c, n);
    iter_kernel<false><<<node_blocks, 256>>>(tmp, bsum, deg, adj, xn, c, cnew, n);
    // (9) re-normalize for layer 2
    norm_kernel<<<node_blocks, 256>>>(cnew, xn, n);
    // (10..12) layer 2 routing
    iter_kernel<true ><<<node_blocks, 256>>>(tmp, bsum, deg, adj, xn, xn, c, n);
    iter_kernel<true ><<<node_blocks, 256>>>(tmp, bsum, deg, adj, xn, c, c, n);
    iter_kernel<false><<<node_blocks, 256>>>(tmp, bsum, deg, adj, xn, c, cnew, n);

    // out = x @ mlp_w + mlp_b
    gemm_bias_kernel<<<G1, 128>>>(cnew, mlp_w, mlp_b, (float*)d_out, n);
    // second tuple element: x
    if (out_size >= 2 * n * D)
        cudaMemcpyAsync((float*)d_out + (size_t)n * D, cnew, nbytes,
                        cudaMemcpyDeviceToDevice, 0);
}

// round 13
// speedup vs baseline: 1.5942x; 1.5942x over previous
#include <cuda_runtime.h>
#include <cstdint>

#define N_MAX 50000
#define M_MAX 800000
#define D 128
#define SCAN_BS 512

// Scratch — __device__ globals only (no allocs allowed).
__device__ __align__(16) static float g_bufA[N_MAX * D];   // x after input GEMM
__device__ __align__(16) static float g_xn[N_MAX * D];     // normalized layer input
__device__ __align__(16) static float g_c[N_MAX * D];      // current normalized routing state
__device__ __align__(16) static float g_cnew[N_MAX * D];   // layer output (unnormalized)
__device__ static int g_src[M_MAX];
__device__ static int g_trg[M_MAX];
__device__ static int g_deg[N_MAX];
__device__ static int g_cnt[N_MAX];
__device__ static int g_tmp[N_MAX];          // block-local exclusive scan
__device__ static int g_bsum[256];           // per-block sums
__device__ static int g_rowptr[N_MAX + 1];
__device__ static int g_adj[M_MAX];          // incoming-edge src ids grouped by trg

// -------------------------------------------- idx convert + degree histogram
// edge_index is int32 (established R1/R2: int64 interpretation faults; int32 passes).
__global__ void idx_hist_kernel(const int* __restrict__ ei,
                                int* __restrict__ src, int* __restrict__ trg,
                                int* __restrict__ deg, int m) {
    int i = blockIdx.x * blockDim.x + threadIdx.x;
    if (i >= m) return;
    int s = ei[i];
    int t = ei[m + i];
    src[i] = s;
    trg[i] = t;
    atomicAdd(&deg[t], 1);
}

// Phase 1: per-block exclusive scan (Hillis-Steele) + block sum.
__global__ void scan_block_kernel(const int* __restrict__ deg, int* __restrict__ tmp,
                                  int* __restrict__ bsum, int n) {
    __shared__ int sm[SCAN_BS];
    int t = threadIdx.x;
    int i = blockIdx.x * SCAN_BS + t;
    int v = (i < n) ? deg[i] : 0;
    sm[t] = v;
    __syncthreads();
    for (int off = 1; off < SCAN_BS; off <<= 1) {
        int y = (t >= off) ? sm[t - off] : 0;
        __syncthreads();
        sm[t] += y;
        __syncthreads();
    }
    if (i < n) tmp[i] = sm[t] - v;              // exclusive
    if (t == SCAN_BS - 1) bsum[blockIdx.x] = sm[t];
}

// Phase 2: exclusive scan of block sums (nb <= 256), single block.
__global__ void scan_bsum_kernel(int* __restrict__ bsum, int nb) {
    __shared__ int sm[256];
    int t = threadIdx.x;
    int v = (t < nb) ? bsum[t] : 0;
    sm[t] = v;
    __syncthreads();
    for (int off = 1; off < 256; off <<= 1) {
        int y = (t >= off) ? sm[t - off] : 0;
        __syncthreads();
        sm[t] += y;
        __syncthreads();
    }
    if (t < nb) bsum[t] = sm[t] - v;            // exclusive
}

// Phase 3: rowptr[i] = tmp[i] + bsum[i/SCAN_BS]; rowptr[n] = m.
__global__ void scan_add_kernel(const int* __restrict__ tmp, const int* __restrict__ bsum,
                                int* __restrict__ rowptr, int n, int m) {
    int i = blockIdx.x * blockDim.x + threadIdx.x;
    if (i < n) rowptr[i] = tmp[i] + bsum[i / SCAN_BS];
    if (i == 0) rowptr[n] = m;
}

__global__ void scatter_kernel(const int* __restrict__ src, const int* __restrict__ trg,
                               const int* __restrict__ rowptr, int* __restrict__ cnt,
                               int* __restrict__ adj, int m) {
    int i = blockIdx.x * blockDim.x + threadIdx.x;
    if (i >= m) return;
    int tg = trg[i];
    int pos = rowptr[tg] + atomicAdd(&cnt[tg], 1);
    adj[pos] = src[i];
}

// ---------------------------------------------------------------- GEMM + bias
#define BM 32
__global__ void gemm_bias_kernel(const float* __restrict__ A,
                                 const float* __restrict__ W,
                                 const float* __restrict__ b,
                                 float* __restrict__ C, int n) {
    __shared__ float As[BM * D];
    int j = threadIdx.x;
    int row0 = blockIdx.x * BM;
    int nvalid = n - row0; if (nvalid > BM) nvalid = BM;

    const float4* A4 = (const float4*)(A + (size_t)row0 * D);
    float4* As4 = (float4*)As;
    for (int i = threadIdx.x; i < nvalid * (D / 4); i += blockDim.x) As4[i] = A4[i];
    __syncthreads();

    float acc[BM];
#pragma unroll
    for (int r = 0; r < BM; r++) acc[r] = 0.f;
    for (int k = 0; k < D; k++) {
        float w = W[k * D + j];
#pragma unroll
        for (int r = 0; r < BM; r++) acc[r] = fmaf(As[r * D + k], w, acc[r]);
    }
    float bj = b[j];
    for (int r = 0; r < nvalid; r++) C[(size_t)(row0 + r) * D + j] = acc[r] + bj;
}

// ------------------------------------------------------- channel normalize
__global__ void norm_kernel(const float* __restrict__ in, float* __restrict__ out, int n) {
    int gw = (blockIdx.x * blockDim.x + threadIdx.x) >> 5;
    if (gw >= n) return;
    int lane = threadIdx.x & 31;
    float4 v = *(const float4*)(in + (size_t)gw * D + lane * 4);
    float ss = v.x * v.x + v.y * v.y + v.z * v.z + v.w * v.w;
    ss += __shfl_xor_sync(0xffffffffu, ss, 1);
    ss += __shfl_xor_sync(0xffffffffu, ss, 2);
    ss += __shfl_xor_sync(0xffffffffu, ss, 4);
    float inv = 1.0f / fmaxf(sqrtf(ss), 1e-12f);
    *(float4*)(out + (size_t)gw * D + lane * 4) =
        make_float4(v.x * inv, v.y * inv, v.z * inv, v.w * inv);
}

// ------------------------------------------- fused routing iteration (R9 body)
// warp per target node v; TWO edges per warp-iteration (16 lanes each).
template <bool DO_NORM>
__global__ void iter_kernel(const int* __restrict__ rowptr, const int* __restrict__ adj,
                            const float* __restrict__ xn, const float* __restrict__ c,
                            float* __restrict__ out, int n) {
    int v = (blockIdx.x * blockDim.x + threadIdx.x) >> 5;
    if (v >= n) return;
    int lane = threadIdx.x & 31;
    int half = lane >> 4;
    int q = lane & 3;
    int ch = (lane & 15) >> 2;
    int dbase = ch * 32 + q * 8;

    // s[a] = sum of c[v][4a..4a+3]; lane a holds sv. Redistribute 8 per lane.
    float4 cv = *(const float4*)(c + (size_t)v * D + lane * 4);
    float sv = cv.x + cv.y + cv.z + cv.w;
    float sr[8];
#pragma unroll
    for (int j = 0; j < 8; j++)
        sr[j] = __shfl_sync(0xffffffffu, sv, q * 8 + j);

    // residual into half 0 only (merge would double-count otherwise)
    float4 a0 = make_float4(0.f, 0.f, 0.f, 0.f);
    float4 a1 = make_float4(0.f, 0.f, 0.f, 0.f);
    if (half == 0) {
        a0 = *(const float4*)(xn + (size_t)v * D + dbase);
        a1 = *(const float4*)(xn + (size_t)v * D + dbase + 4);
    }

    int beg = rowptr[v], end = rowptr[v + 1];
    int nit = (end - beg + 1) >> 1;
    for (int j = 0; j < nit; j++) {
        int e = beg + 2 * j + half;
        bool valid = (e < end);
        int s = adj[valid ? e : beg];
        const float* zp = xn + (size_t)s * D + dbase;
        float4 z0 = *(const float4*)(zp);
        float4 z1 = *(const float4*)(zp + 4);

        float p = z0.x * sr[0] + z0.y * sr[1] + z0.z * sr[2] + z0.w * sr[3]
                + z1.x * sr[4] + z1.y * sr[5] + z1.z * sr[6] + z1.w * sr[7];
        p += __shfl_xor_sync(0xffffffffu, p, 1);
        p += __shfl_xor_sync(0xffffffffu, p, 2);       // p = logit for channel ch
        float mx = fmaxf(p, __shfl_xor_sync(0xffffffffu, p, 4));
        mx = fmaxf(mx, __shfl_xor_sync(0xffffffffu, mx, 8));
        float ex = __expf(p - mx);
        float den = ex + __shfl_xor_sync(0xffffffffu, ex, 4);
        den += __shfl_xor_sync(0xffffffffu, den, 8);
        float w = valid ? __fdividef(ex, den) : 0.f;

        a0.x = fmaf(w, z0.x, a0.x);
        a0.y = fmaf(w, z0.y, a0.y);
        a0.z = fmaf(w, z0.z, a0.z);
        a0.w = fmaf(w, z0.w, a0.w);
        a1.x = fmaf(w, z1.x, a1.x);
        a1.y = fmaf(w, z1.y, a1.y);
        a1.z = fmaf(w, z1.z, a1.z);
        a1.w = fmaf(w, z1.w, a1.w);
    }

    // merge halves
    a0.x += __shfl_xor_sync(0xffffffffu, a0.x, 16);
    a0.y += __shfl_xor_sync(0xffffffffu, a0.y, 16);
    a0.z += __shfl_xor_sync(0xffffffffu, a0.z, 16);
    a0.w += __shfl_xor_sync(0xffffffffu, a0.w, 16);
    a1.x += __shfl_xor_sync(0xffffffffu, a1.x, 16);
    a1.y += __shfl_xor_sync(0xffffffffu, a1.y, 16);
    a1.z += __shfl_xor_sync(0xffffffffu, a1.z, 16);
    a1.w += __shfl_xor_sync(0xffffffffu, a1.w, 16);

    if (DO_NORM) {
        float ss = a0.x * a0.x + a0.y * a0.y + a0.z * a0.z + a0.w * a0.w
                 + a1.x * a1.x + a1.y * a1.y + a1.z * a1.z + a1.w * a1.w;
        ss += __shfl_xor_sync(0xffffffffu, ss, 1);
        ss += __shfl_xor_sync(0xffffffffu, ss, 2);
        float inv = 1.0f / fmaxf(sqrtf(ss), 1e-12f);
        a0.x *= inv; a0.y *= inv; a0.z *= inv; a0.w *= inv;
        a1.x *= inv; a1.y *= inv; a1.z *= inv; a1.w *= inv;
    }

    if (half == 0) {
        *(float4*)(out + (size_t)v * D + dbase)     = a0;
        *(float4*)(out + (size_t)v * D + dbase + 4) = a1;
    }
}

// ---------------------------------------------------------------- launch
extern "C" void kernel_launch(void* const* d_in, const int* in_sizes, int n_in,
                              void* d_out, int out_size) {
    const float* feat  = (const float*)d_in[0];
    const int*   ei    = (const int*)d_in[1];
    const float* lin_w = (const float*)d_in[2];
    const float* lin_b = (const float*)d_in[3];
    const float* mlp_w = (const float*)d_in[4];
    const float* mlp_b = (const float*)d_in[5];

    int n = in_sizes[0] / D;
    int m = in_sizes[1] / 2;

    float *bufA, *xn, *c, *cnew;
    int *src, *trg, *deg, *cnt, *tmp, *bsum, *rowptr, *adj;
    cudaGetSymbolAddress((void**)&bufA,   g_bufA);
    cudaGetSymbolAddress((void**)&xn,     g_xn);
    cudaGetSymbolAddress((void**)&c,      g_c);
    cudaGetSymbolAddress((void**)&cnew,   g_cnew);
    cudaGetSymbolAddress((void**)&src,    g_src);
    cudaGetSymbolAddress((void**)&trg,    g_trg);
    cudaGetSymbolAddress((void**)&deg,    g_deg);
    cudaGetSymbolAddress((void**)&cnt,    g_cnt);
    cudaGetSymbolAddress((void**)&tmp,    g_tmp);
    cudaGetSymbolAddress((void**)&bsum,   g_bsum);
    cudaGetSymbolAddress((void**)&rowptr, g_rowptr);
    cudaGetSymbolAddress((void**)&adj,    g_adj);

    // ---- edge preprocessing + CSR build (once per call)
    cudaMemsetAsync(deg, 0, (size_t)n * sizeof(int), 0);
    cudaMemsetAsync(cnt, 0, (size_t)n * sizeof(int), 0);
    idx_hist_kernel<<<(m + 255) / 256, 256>>>(ei, src, trg, deg, m);
    int nb = (n + SCAN_BS - 1) / SCAN_BS;
    scan_block_kernel<<<nb, SCAN_BS>>>(deg, tmp, bsum, n);
    scan_bsum_kernel<<<1, 256>>>(bsum, nb);
    scan_add_kernel<<<(n + 255) / 256, 256>>>(tmp, bsum, rowptr, n, m);
    scatter_kernel<<<(m + 255) / 256, 256>>>(src, trg, rowptr, cnt, adj, m);

    // ---- x = feat @ lin_w + lin_b
    gemm_bias_kernel<<<(n + BM - 1) / BM, 128>>>(feat, lin_w, lin_b, bufA, n);

    int node_blocks = (n * 32 + 255) / 256;  // warp per node
    size_t nbytes = (size_t)n * D * sizeof(float);

    const float* x_in = bufA;
    for (int layer = 0; layer < 2; layer++) {
        norm_kernel<<<node_blocks, 256>>>(x_in, xn, n);
        iter_kernel<true ><<<node_blocks, 256>>>(rowptr, adj, xn, xn, c, n);   // t=0 (c==xn)
        iter_kernel<true ><<<node_blocks, 256>>>(rowptr, adj, xn, c, c, n);    // t=1
        iter_kernel<false><<<node_blocks, 256>>>(rowptr, adj, xn, c, cnew, n); // t=2 raw
        x_in = cnew;
    }

    // out = x @ mlp_w + mlp_b
    gemm_bias_kernel<<<(n + BM - 1) / BM, 128>>>(cnew, mlp_w, mlp_b, (float*)d_out, n);
    // second tuple element: x
    if (out_size >= 2 * n * D)
        cudaMemcpyAsync((float*)d_out + (size_t)n * D, cnew, nbytes,
                        cudaMemcpyDeviceToDevice, 0);
}